// round 9
// baseline (speedup 1.0000x reference)
#include <cuda_runtime.h>
#include <cuda_bf16.h>

#define N_NODES 100000
#define N_EDGES 3200000
#define IN_FEAT 512
#define HID 32
#define SCAN_BLK 512
#define SCAN_NBLK ((N_NODES + SCAN_BLK - 1) / SCAN_BLK)   // 196

// ---------------- device scratch (static, no allocation) ----------------
__device__ int   g_degi[N_NODES];
__device__ float g_dinv[N_NODES];
__device__ int   g_rowstart[N_NODES + 1];
__device__ int   g_cursor[N_NODES];
__device__ int   g_blocksum[SCAN_NBLK];
__device__ int   g_blockoff[SCAN_NBLK];
__device__ int   g_csrc[N_EDGES];
__device__ float g_h[(size_t)N_NODES * HID];    // ping
__device__ float g_agg[(size_t)N_NODES * HID];  // pong

// ---------------- f32x2 helpers ----------------
__device__ __forceinline__ unsigned long long fma2(unsigned long long a,
                                                   unsigned long long b,
                                                   unsigned long long c) {
    unsigned long long d;
    asm("fma.rn.f32x2 %0, %1, %2, %3;" : "=l"(d) : "l"(a), "l"(b), "l"(c));
    return d;
}
__device__ __forceinline__ unsigned long long pack2(float lo, float hi) {
    unsigned long long d;
    asm("mov.b64 %0, {%1, %2};" : "=l"(d) : "f"(lo), "f"(hi));
    return d;
}
__device__ __forceinline__ void unpack2(unsigned long long v, float& lo, float& hi) {
    asm("mov.b64 {%0, %1}, %2;" : "=f"(lo), "=f"(hi) : "l"(v));
}

// ---------------- degree / CSR build ----------------
__global__ void zero_degi_kernel() {
    int i = blockIdx.x * blockDim.x + threadIdx.x;
    if (i < N_NODES) g_degi[i] = 0;
}

__global__ void degi_kernel(const int* __restrict__ dst) {
    int e = blockIdx.x * blockDim.x + threadIdx.x;
    if (e < N_EDGES) atomicAdd(&g_degi[dst[e]], 1);
}

// block-local exclusive scan of degrees; also computes dinv (fused).
__global__ void scan_block_kernel() {
    __shared__ int sh[SCAN_BLK];
    int i = blockIdx.x * SCAN_BLK + threadIdx.x;
    int v = (i < N_NODES) ? g_degi[i] : 0;
    if (i < N_NODES) g_dinv[i] = rsqrtf((float)v + 1.0f);
    sh[threadIdx.x] = v;
    __syncthreads();
    #pragma unroll
    for (int off = 1; off < SCAN_BLK; off <<= 1) {
        int t = (threadIdx.x >= off) ? sh[threadIdx.x - off] : 0;
        __syncthreads();
        sh[threadIdx.x] += t;
        __syncthreads();
    }
    if (i < N_NODES) g_rowstart[i] = sh[threadIdx.x] - v;   // exclusive, block-local
    if (threadIdx.x == SCAN_BLK - 1) g_blocksum[blockIdx.x] = sh[SCAN_BLK - 1];
}

// parallel scan of the 196 block sums (single 256-thread block).
__global__ void scan_tops_kernel() {
    __shared__ int sh[256];
    int t = threadIdx.x;
    int v = (t < SCAN_NBLK) ? g_blocksum[t] : 0;
    sh[t] = v;
    __syncthreads();
    #pragma unroll
    for (int off = 1; off < 256; off <<= 1) {
        int x = (t >= off) ? sh[t - off] : 0;
        __syncthreads();
        sh[t] += x;
        __syncthreads();
    }
    if (t < SCAN_NBLK) g_blockoff[t] = sh[t] - v;   // exclusive
    if (t == 255) g_rowstart[N_NODES] = sh[255];    // == N_EDGES
}

__global__ void scan_add_kernel() {
    int i = blockIdx.x * blockDim.x + threadIdx.x;
    if (i < N_NODES) {
        int v = g_rowstart[i] + g_blockoff[i >> 9];   // 512 = 1<<9
        g_rowstart[i] = v;
        g_cursor[i] = v;
    }
}

__global__ void fill_kernel(const int* __restrict__ src, const int* __restrict__ dst) {
    int e = blockIdx.x * blockDim.x + threadIdx.x;
    if (e < N_EDGES) {
        int d = dst[e];
        int pos = atomicAdd(&g_cursor[d], 1);
        g_csrc[pos] = src[e];
    }
}

// ---------------- GEMM1: [N,512] @ [512,32], f32x2 packed ----------------
// 128 threads/block, tile = 128 rows x 32 cols (smaller tile -> ~2x occupancy
// vs 256-row version: acc 2x8 pairs = 32 regs, 12 KB smem, 782 CTAs).
// Thread: 4 rows (2 f32x2 pairs) x 8 cols. W duplicated to float2 in shared ->
// LDS.64 broadcast; each W load feeds 2 FMA2. Epilogue scales by dinv[row].
// Xs row pitch = 16 floats (64 B) so float4 slices stay 16B-aligned.
#define G1_ROWS 128
#define G1_TK 16
__global__ __launch_bounds__(128) void gemm1_kernel(
    const float* __restrict__ x, const float* __restrict__ W,
    float* __restrict__ hh)
{
    __shared__ float  Xs[G1_ROWS][G1_TK];       // 8 KB
    __shared__ float2 Ws2[G1_TK][HID];          // 4 KB

    int tid = threadIdx.x;
    int cid = tid & 3;          // col group: cols cid*8 .. cid*8+7
    int rid = tid >> 2;         // 0..31: rows rid*4 .. rid*4+3
    int rowbase = blockIdx.x * G1_ROWS;

    unsigned long long acc[2][8];
    #pragma unroll
    for (int p = 0; p < 2; p++)
        #pragma unroll
        for (int c = 0; c < 8; c++) acc[p][c] = 0ull;

    for (int k0 = 0; k0 < IN_FEAT; k0 += G1_TK) {
        // load X tile: 128 rows x 16 k = 512 float4, 4 per thread, coalesced
        #pragma unroll
        for (int i = 0; i < 4; i++) {
            int flat = tid + i * 128;            // 0..511
            int r  = flat >> 2;
            int c4 = flat & 3;
            int gr = rowbase + r;
            if (gr >= N_NODES) gr = N_NODES - 1;
            float4 v = *(const float4*)(x + (size_t)gr * IN_FEAT + k0 + c4 * 4);
            *(float4*)(&Xs[r][c4 * 4]) = v;
        }
        // load W tile duplicated: Ws2[kk][c] = (w, w)
        #pragma unroll
        for (int i = 0; i < 4; i++) {
            int idx = tid + i * 128;             // 0..511
            int kk = idx >> 5;
            int c  = idx & 31;
            float w = W[(size_t)(k0 + kk) * HID + c];
            Ws2[kk][c] = make_float2(w, w);
        }
        __syncthreads();

        #pragma unroll
        for (int kk4 = 0; kk4 < G1_TK; kk4 += 4) {
            unsigned long long xp[2][4];
            #pragma unroll
            for (int p = 0; p < 2; p++) {
                float4 xa = *(const float4*)(&Xs[rid * 4 + 2 * p + 0][kk4]);
                float4 xb = *(const float4*)(&Xs[rid * 4 + 2 * p + 1][kk4]);
                xp[p][0] = pack2(xa.x, xb.x);
                xp[p][1] = pack2(xa.y, xb.y);
                xp[p][2] = pack2(xa.z, xb.z);
                xp[p][3] = pack2(xa.w, xb.w);
            }
            #pragma unroll
            for (int kkk = 0; kkk < 4; kkk++) {
                #pragma unroll
                for (int c = 0; c < 8; c++) {
                    unsigned long long wp =
                        *(const unsigned long long*)(&Ws2[kk4 + kkk][cid * 8 + c]);
                    #pragma unroll
                    for (int p = 0; p < 2; p++)
                        acc[p][c] = fma2(xp[p][kkk], wp, acc[p][c]);
                }
            }
        }
        __syncthreads();
    }

    #pragma unroll
    for (int p = 0; p < 2; p++) {
        int r0 = rowbase + rid * 4 + 2 * p;
        int r1 = r0 + 1;
        float lo[8], hi[8];
        #pragma unroll
        for (int c = 0; c < 8; c++) unpack2(acc[p][c], lo[c], hi[c]);
        if (r0 < N_NODES) {
            float d0 = g_dinv[r0];
            float4 v0 = make_float4(lo[0]*d0, lo[1]*d0, lo[2]*d0, lo[3]*d0);
            float4 v1 = make_float4(lo[4]*d0, lo[5]*d0, lo[6]*d0, lo[7]*d0);
            *(float4*)(hh + (size_t)r0 * HID + cid * 8 + 0) = v0;
            *(float4*)(hh + (size_t)r0 * HID + cid * 8 + 4) = v1;
        }
        if (r1 < N_NODES) {
            float d1 = g_dinv[r1];
            float4 v0 = make_float4(hi[0]*d1, hi[1]*d1, hi[2]*d1, hi[3]*d1);
            float4 v1 = make_float4(hi[4]*d1, hi[5]*d1, hi[6]*d1, hi[7]*d1);
            *(float4*)(hh + (size_t)r1 * HID + cid * 8 + 0) = v0;
            *(float4*)(hh + (size_t)r1 * HID + cid * 8 + 4) = v1;
        }
    }
}

// ---------------- fused gather + next-layer GEMM ----------------
__global__ __launch_bounds__(256) void gather_gemm_kernel(
    const float* __restrict__ hh_in, const float* __restrict__ b,
    const float* __restrict__ W, float* __restrict__ hh_out)
{
    __shared__ float Ws[HID * HID];   // Ws[k*32 + col] = W[k][col]
    for (int i = threadIdx.x; i < HID * HID; i += 256) Ws[i] = W[i];
    __syncthreads();

    int node = blockIdx.x * 8 + (threadIdx.x >> 5);
    int lane = threadIdx.x & 31;
    int start = g_rowstart[node];
    int end   = g_rowstart[node + 1];

    float acc0 = 0.f, acc1 = 0.f;
    for (int base = start; base < end; base += 32) {
        int e = base + lane;
        int sidx = (e < end) ? g_csrc[e] : 0;
        int n = end - base;
        if (n >= 32) {
            #pragma unroll
            for (int j = 0; j < 32; j += 2) {
                int s0 = __shfl_sync(0xffffffffu, sidx, j);
                int s1 = __shfl_sync(0xffffffffu, sidx, j + 1);
                acc0 += hh_in[(size_t)s0 * HID + lane];
                acc1 += hh_in[(size_t)s1 * HID + lane];
            }
        } else {
            for (int j = 0; j < n; j++) {
                int s = __shfl_sync(0xffffffffu, sidx, j);
                acc0 += hh_in[(size_t)s * HID + lane];
            }
        }
    }
    float dv = g_dinv[node];
    float self = hh_in[(size_t)node * HID + lane];
    float v = fmaxf(dv * (acc0 + acc1 + self) + b[lane], 0.0f);

    float o = 0.f;
    #pragma unroll
    for (int k = 0; k < HID; k++) {
        float xv = __shfl_sync(0xffffffffu, v, k);
        o += xv * Ws[k * HID + lane];
    }
    hh_out[(size_t)node * HID + lane] = o * dv;
}

// ---------------- fused layer-3 gather + MLP head ----------------
__global__ __launch_bounds__(256) void gather_mlp_kernel(
    const float* __restrict__ hh, const float* __restrict__ b3,
    const float* __restrict__ l1W, const float* __restrict__ l1b,
    const float* __restrict__ l2W, const float* __restrict__ l2b,
    float* __restrict__ out)
{
    int node = blockIdx.x * 8 + (threadIdx.x >> 5);
    int lane = threadIdx.x & 31;
    int start = g_rowstart[node];
    int end   = g_rowstart[node + 1];

    float acc0 = 0.f, acc1 = 0.f;
    for (int base = start; base < end; base += 32) {
        int e = base + lane;
        int sidx = (e < end) ? g_csrc[e] : 0;
        int n = end - base;
        if (n >= 32) {
            #pragma unroll
            for (int j = 0; j < 32; j += 2) {
                int s0 = __shfl_sync(0xffffffffu, sidx, j);
                int s1 = __shfl_sync(0xffffffffu, sidx, j + 1);
                acc0 += hh[(size_t)s0 * HID + lane];
                acc1 += hh[(size_t)s1 * HID + lane];
            }
        } else {
            for (int j = 0; j < n; j++) {
                int s = __shfl_sync(0xffffffffu, sidx, j);
                acc0 += hh[(size_t)s * HID + lane];
            }
        }
    }
    float dv = g_dinv[node];
    float self = hh[(size_t)node * HID + lane];
    float v = fmaxf(dv * (acc0 + acc1 + self) + b3[lane], 0.0f);  // x3

    // lin1: [32] -> [16], relu
    float a1 = 0.f;
    #pragma unroll
    for (int k = 0; k < 32; k++) {
        float xv = __shfl_sync(0xffffffffu, v, k);
        if (lane < 16) a1 += xv * l1W[k * 16 + lane];
    }
    float h1 = (lane < 16) ? fmaxf(a1 + l1b[lane], 0.0f) : 0.0f;

    // lin2: [16] -> [10]
    float a2 = 0.f;
    #pragma unroll
    for (int j = 0; j < 16; j++) {
        float hv = __shfl_sync(0xffffffffu, h1, j);
        if (lane < 10) a2 += hv * l2W[j * 10 + lane];
    }
    if (lane < 10) out[(size_t)node * 10 + lane] = a2 + l2b[lane];
}

// ---------------- host ----------------
extern "C" void kernel_launch(void* const* d_in, const int* in_sizes, int n_in,
                              void* d_out, int out_size)
{
    const float* x0  = (const float*)d_in[0];
    const int*   ei  = (const int*)d_in[1];   // edge_index int32
    // d_in[2] = batch (unused)
    const float* W1  = (const float*)d_in[3];
    const float* b1  = (const float*)d_in[4];
    const float* W2  = (const float*)d_in[5];
    const float* b2  = (const float*)d_in[6];
    const float* W3  = (const float*)d_in[7];
    const float* b3  = (const float*)d_in[8];
    const float* l1W = (const float*)d_in[9];
    const float* l1b = (const float*)d_in[10];
    const float* l2W = (const float*)d_in[11];
    const float* l2b = (const float*)d_in[12];
    float* out = (float*)d_out;

    const int* src = ei;
    const int* dst = ei + N_EDGES;

    float *hbuf = nullptr, *abuf = nullptr;
    cudaGetSymbolAddress((void**)&hbuf, g_h);
    cudaGetSymbolAddress((void**)&abuf, g_agg);

    // one-time infra (streams/events are not device memory; work per call is
    // identical and fully captured into the graph via fork-join events)
    static cudaStream_t s_side = nullptr;
    static cudaEvent_t  s_fork = nullptr, s_join = nullptr;
    if (s_side == nullptr) {
        cudaStreamCreateWithFlags(&s_side, cudaStreamNonBlocking);
        cudaEventCreateWithFlags(&s_fork, cudaEventDisableTiming);
        cudaEventCreateWithFlags(&s_join, cudaEventDisableTiming);
    }

    const int nodeBlocks = (N_NODES + 255) / 256;   // 391
    const int edgeBlocks = N_EDGES / 256;           // 12500
    const int warpBlocks = N_NODES / 8;             // 12500
    const int g1Blocks   = (N_NODES + G1_ROWS - 1) / G1_ROWS;  // 782

    // ---- CSR build prefix (degrees + dinv) ----
    zero_degi_kernel<<<nodeBlocks, 256>>>();
    degi_kernel<<<edgeBlocks, 256>>>(dst);
    scan_block_kernel<<<SCAN_NBLK, SCAN_BLK>>>();   // also computes dinv

    // ---- fork: gemm1 needs only dinv; CSR tail is independent ----
    cudaEventRecord(s_fork, 0);
    cudaStreamWaitEvent(s_side, s_fork, 0);
    gemm1_kernel<<<g1Blocks, 128, 0, s_side>>>(x0, W1, hbuf);       // hh1

    scan_tops_kernel<<<1, 256>>>();
    scan_add_kernel<<<nodeBlocks, 256>>>();
    fill_kernel<<<edgeBlocks, 256>>>(src, dst);

    // ---- join: gathers need both CSR and hh1 ----
    cudaEventRecord(s_join, s_side);
    cudaStreamWaitEvent(0, s_join, 0);

    // ---- gather1 + gemm2 fused ----
    gather_gemm_kernel<<<warpBlocks, 256>>>(hbuf, b1, W2, abuf);    // hh2

    // ---- gather2 + gemm3 fused ----
    gather_gemm_kernel<<<warpBlocks, 256>>>(abuf, b2, W3, hbuf);    // hh3

    // ---- gather3 + MLP head fused ----
    gather_mlp_kernel<<<warpBlocks, 256>>>(hbuf, b3, l1W, l1b, l2W, l2b, out);
}

// round 10
// speedup vs baseline: 1.3683x; 1.3683x over previous
#include <cuda_runtime.h>
#include <cuda_bf16.h>

#define N_NODES 100000
#define N_EDGES 3200000
#define IN_FEAT 512
#define HID 32
#define SCAN_BLK 512
#define SCAN_NBLK ((N_NODES + SCAN_BLK - 1) / SCAN_BLK)   // 196

// ---------------- device scratch (static, no allocation) ----------------
__device__ int   g_degi[N_NODES];
__device__ float g_dinv[N_NODES];
__device__ int   g_rowstart[N_NODES + 1];
__device__ int   g_cursor[N_NODES];
__device__ int   g_blocksum[SCAN_NBLK];
__device__ int   g_blockoff[SCAN_NBLK];
__device__ int   g_csrc[N_EDGES];
__device__ float g_h[(size_t)N_NODES * HID];    // ping
__device__ float g_agg[(size_t)N_NODES * HID];  // pong

// ---------------- f32x2 helpers ----------------
__device__ __forceinline__ unsigned long long fma2(unsigned long long a,
                                                   unsigned long long b,
                                                   unsigned long long c) {
    unsigned long long d;
    asm("fma.rn.f32x2 %0, %1, %2, %3;" : "=l"(d) : "l"(a), "l"(b), "l"(c));
    return d;
}
__device__ __forceinline__ void unpack2(unsigned long long v, float& lo, float& hi) {
    asm("mov.b64 {%0, %1}, %2;" : "=f"(lo), "=f"(hi) : "l"(v));
}

// ---------------- degree / CSR build ----------------
__global__ void zero_degi_kernel() {
    int i = blockIdx.x * blockDim.x + threadIdx.x;
    if (i < N_NODES) g_degi[i] = 0;
}

__global__ void degi_kernel(const int* __restrict__ dst) {
    int e = blockIdx.x * blockDim.x + threadIdx.x;
    if (e < N_EDGES) atomicAdd(&g_degi[dst[e]], 1);
}

// block-local exclusive scan of degrees; also computes dinv (fused).
__global__ void scan_block_kernel() {
    __shared__ int sh[SCAN_BLK];
    int i = blockIdx.x * SCAN_BLK + threadIdx.x;
    int v = (i < N_NODES) ? g_degi[i] : 0;
    if (i < N_NODES) g_dinv[i] = rsqrtf((float)v + 1.0f);
    sh[threadIdx.x] = v;
    __syncthreads();
    #pragma unroll
    for (int off = 1; off < SCAN_BLK; off <<= 1) {
        int t = (threadIdx.x >= off) ? sh[threadIdx.x - off] : 0;
        __syncthreads();
        sh[threadIdx.x] += t;
        __syncthreads();
    }
    if (i < N_NODES) g_rowstart[i] = sh[threadIdx.x] - v;   // exclusive, block-local
    if (threadIdx.x == SCAN_BLK - 1) g_blocksum[blockIdx.x] = sh[SCAN_BLK - 1];
}

// parallel scan of the 196 block sums (single 256-thread block).
__global__ void scan_tops_kernel() {
    __shared__ int sh[256];
    int t = threadIdx.x;
    int v = (t < SCAN_NBLK) ? g_blocksum[t] : 0;
    sh[t] = v;
    __syncthreads();
    #pragma unroll
    for (int off = 1; off < 256; off <<= 1) {
        int x = (t >= off) ? sh[t - off] : 0;
        __syncthreads();
        sh[t] += x;
        __syncthreads();
    }
    if (t < SCAN_NBLK) g_blockoff[t] = sh[t] - v;   // exclusive
    if (t == 255) g_rowstart[N_NODES] = sh[255];    // == N_EDGES
}

__global__ void scan_add_kernel() {
    int i = blockIdx.x * blockDim.x + threadIdx.x;
    if (i < N_NODES) {
        int v = g_rowstart[i] + g_blockoff[i >> 9];   // 512 = 1<<9
        g_rowstart[i] = v;
        g_cursor[i] = v;
    }
}

__global__ void fill_kernel(const int* __restrict__ src, const int* __restrict__ dst) {
    int e = blockIdx.x * blockDim.x + threadIdx.x;
    if (e < N_EDGES) {
        int d = dst[e];
        int pos = atomicAdd(&g_cursor[d], 1);
        g_csrc[pos] = src[e];
    }
}

// ---------------- GEMM1: [N,512] @ [512,32], f32x2 packed ----------------
// 128 threads/block, tile = 256 rows x 32 cols.
// Shared X is PRE-PACKED as row-pair float2: Xp[kk][pair] = (X[2p][kk], X[2p+1][kk]).
// Inner loop is pure LDS.64 -> FFMA2: no pack MOVs, 2-way conflicts max.
// Thread (cid, rid): pairs rid*4..rid*4+3 (rows rid*8..rid*8+7), cols cid*8..cid*8+7.
// W duplicated to (w,w) float2 -> LDS.64 broadcast, conflict-free.
// Epilogue scales by dinv[row] (hh = (x@W) * dinv).
#define G1_ROWS 256
#define G1_TK 16
__global__ __launch_bounds__(128) void gemm1_kernel(
    const float* __restrict__ x, const float* __restrict__ W,
    float* __restrict__ hh)
{
    __shared__ float2 Xp[G1_TK][G1_ROWS / 2];   // 16 KB
    __shared__ float2 Ws2[G1_TK][HID];          // 4 KB

    int tid = threadIdx.x;
    int cid = tid & 3;          // col group: cols cid*8 .. cid*8+7
    int rid = tid >> 2;         // 0..31: pairs rid*4 .. rid*4+3
    int rowbase = blockIdx.x * G1_ROWS;

    unsigned long long acc[4][8];
    #pragma unroll
    for (int p = 0; p < 4; p++)
        #pragma unroll
        for (int c = 0; c < 8; c++) acc[p][c] = 0ull;

    for (int k0 = 0; k0 < IN_FEAT; k0 += G1_TK) {
        // load X tile: 256 rows x 16 k = 1024 float4, 8 per thread, coalesced.
        // transpose-store into packed pair layout (scalar STS, 4-way conflict,
        // hidden under the FMA2 stream).
        #pragma unroll
        for (int i = 0; i < 8; i++) {
            int flat = tid + i * 128;            // 0..1023
            int r  = flat >> 2;                  // 0..255
            int c4 = flat & 3;                   // 0..3
            int gr = rowbase + r;
            if (gr >= N_NODES) gr = N_NODES - 1;
            float4 v = *(const float4*)(x + (size_t)gr * IN_FEAT + k0 + c4 * 4);
            int pr = r >> 1, comp = r & 1;
            (&Xp[c4 * 4 + 0][pr].x)[comp] = v.x;
            (&Xp[c4 * 4 + 1][pr].x)[comp] = v.y;
            (&Xp[c4 * 4 + 2][pr].x)[comp] = v.z;
            (&Xp[c4 * 4 + 3][pr].x)[comp] = v.w;
        }
        // load W tile duplicated: Ws2[kk][c] = (w, w)
        #pragma unroll
        for (int i = 0; i < 4; i++) {
            int idx = tid + i * 128;             // 0..511
            int kk = idx >> 5;
            int c  = idx & 31;
            float w = W[(size_t)(k0 + kk) * HID + c];
            Ws2[kk][c] = make_float2(w, w);
        }
        __syncthreads();

        #pragma unroll
        for (int kk = 0; kk < G1_TK; kk++) {
            unsigned long long xp[4];
            #pragma unroll
            for (int p = 0; p < 4; p++)
                xp[p] = *(const unsigned long long*)(&Xp[kk][rid * 4 + p]);
            #pragma unroll
            for (int c = 0; c < 8; c++) {
                unsigned long long wp =
                    *(const unsigned long long*)(&Ws2[kk][cid * 8 + c]);
                #pragma unroll
                for (int p = 0; p < 4; p++)
                    acc[p][c] = fma2(xp[p], wp, acc[p][c]);
            }
        }
        __syncthreads();
    }

    // epilogue: unpack, scale by dinv[row], store
    #pragma unroll
    for (int p = 0; p < 4; p++) {
        int r0 = rowbase + (rid * 4 + p) * 2;
        int r1 = r0 + 1;
        float lo[8], hi[8];
        #pragma unroll
        for (int c = 0; c < 8; c++) unpack2(acc[p][c], lo[c], hi[c]);
        if (r0 < N_NODES) {
            float d0 = g_dinv[r0];
            float4 v0 = make_float4(lo[0]*d0, lo[1]*d0, lo[2]*d0, lo[3]*d0);
            float4 v1 = make_float4(lo[4]*d0, lo[5]*d0, lo[6]*d0, lo[7]*d0);
            *(float4*)(hh + (size_t)r0 * HID + cid * 8 + 0) = v0;
            *(float4*)(hh + (size_t)r0 * HID + cid * 8 + 4) = v1;
        }
        if (r1 < N_NODES) {
            float d1 = g_dinv[r1];
            float4 v0 = make_float4(hi[0]*d1, hi[1]*d1, hi[2]*d1, hi[3]*d1);
            float4 v1 = make_float4(hi[4]*d1, hi[5]*d1, hi[6]*d1, hi[7]*d1);
            *(float4*)(hh + (size_t)r1 * HID + cid * 8 + 0) = v0;
            *(float4*)(hh + (size_t)r1 * HID + cid * 8 + 4) = v1;
        }
    }
}

// ---------------- fused gather + next-layer GEMM ----------------
__global__ __launch_bounds__(256) void gather_gemm_kernel(
    const float* __restrict__ hh_in, const float* __restrict__ b,
    const float* __restrict__ W, float* __restrict__ hh_out)
{
    __shared__ float Ws[HID * HID];   // Ws[k*32 + col] = W[k][col]
    for (int i = threadIdx.x; i < HID * HID; i += 256) Ws[i] = W[i];
    __syncthreads();

    int node = blockIdx.x * 8 + (threadIdx.x >> 5);
    int lane = threadIdx.x & 31;
    int start = g_rowstart[node];
    int end   = g_rowstart[node + 1];

    float acc0 = 0.f, acc1 = 0.f;
    for (int base = start; base < end; base += 32) {
        int e = base + lane;
        int sidx = (e < end) ? g_csrc[e] : 0;
        int n = end - base;
        if (n >= 32) {
            #pragma unroll
            for (int j = 0; j < 32; j += 2) {
                int s0 = __shfl_sync(0xffffffffu, sidx, j);
                int s1 = __shfl_sync(0xffffffffu, sidx, j + 1);
                acc0 += hh_in[(size_t)s0 * HID + lane];
                acc1 += hh_in[(size_t)s1 * HID + lane];
            }
        } else {
            for (int j = 0; j < n; j++) {
                int s = __shfl_sync(0xffffffffu, sidx, j);
                acc0 += hh_in[(size_t)s * HID + lane];
            }
        }
    }
    float dv = g_dinv[node];
    float self = hh_in[(size_t)node * HID + lane];
    float v = fmaxf(dv * (acc0 + acc1 + self) + b[lane], 0.0f);

    float o = 0.f;
    #pragma unroll
    for (int k = 0; k < HID; k++) {
        float xv = __shfl_sync(0xffffffffu, v, k);
        o += xv * Ws[k * HID + lane];
    }
    hh_out[(size_t)node * HID + lane] = o * dv;
}

// ---------------- fused layer-3 gather + MLP head ----------------
__global__ __launch_bounds__(256) void gather_mlp_kernel(
    const float* __restrict__ hh, const float* __restrict__ b3,
    const float* __restrict__ l1W, const float* __restrict__ l1b,
    const float* __restrict__ l2W, const float* __restrict__ l2b,
    float* __restrict__ out)
{
    int node = blockIdx.x * 8 + (threadIdx.x >> 5);
    int lane = threadIdx.x & 31;
    int start = g_rowstart[node];
    int end   = g_rowstart[node + 1];

    float acc0 = 0.f, acc1 = 0.f;
    for (int base = start; base < end; base += 32) {
        int e = base + lane;
        int sidx = (e < end) ? g_csrc[e] : 0;
        int n = end - base;
        if (n >= 32) {
            #pragma unroll
            for (int j = 0; j < 32; j += 2) {
                int s0 = __shfl_sync(0xffffffffu, sidx, j);
                int s1 = __shfl_sync(0xffffffffu, sidx, j + 1);
                acc0 += hh[(size_t)s0 * HID + lane];
                acc1 += hh[(size_t)s1 * HID + lane];
            }
        } else {
            for (int j = 0; j < n; j++) {
                int s = __shfl_sync(0xffffffffu, sidx, j);
                acc0 += hh[(size_t)s * HID + lane];
            }
        }
    }
    float dv = g_dinv[node];
    float self = hh[(size_t)node * HID + lane];
    float v = fmaxf(dv * (acc0 + acc1 + self) + b3[lane], 0.0f);  // x3

    // lin1: [32] -> [16], relu
    float a1 = 0.f;
    #pragma unroll
    for (int k = 0; k < 32; k++) {
        float xv = __shfl_sync(0xffffffffu, v, k);
        if (lane < 16) a1 += xv * l1W[k * 16 + lane];
    }
    float h1 = (lane < 16) ? fmaxf(a1 + l1b[lane], 0.0f) : 0.0f;

    // lin2: [16] -> [10]
    float a2 = 0.f;
    #pragma unroll
    for (int j = 0; j < 16; j++) {
        float hv = __shfl_sync(0xffffffffu, h1, j);
        if (lane < 10) a2 += hv * l2W[j * 10 + lane];
    }
    if (lane < 10) out[(size_t)node * 10 + lane] = a2 + l2b[lane];
}

// ---------------- host ----------------
extern "C" void kernel_launch(void* const* d_in, const int* in_sizes, int n_in,
                              void* d_out, int out_size)
{
    const float* x0  = (const float*)d_in[0];
    const int*   ei  = (const int*)d_in[1];   // edge_index int32
    // d_in[2] = batch (unused)
    const float* W1  = (const float*)d_in[3];
    const float* b1  = (const float*)d_in[4];
    const float* W2  = (const float*)d_in[5];
    const float* b2  = (const float*)d_in[6];
    const float* W3  = (const float*)d_in[7];
    const float* b3  = (const float*)d_in[8];
    const float* l1W = (const float*)d_in[9];
    const float* l1b = (const float*)d_in[10];
    const float* l2W = (const float*)d_in[11];
    const float* l2b = (const float*)d_in[12];
    float* out = (float*)d_out;

    const int* src = ei;
    const int* dst = ei + N_EDGES;

    float *hbuf = nullptr, *abuf = nullptr;
    cudaGetSymbolAddress((void**)&hbuf, g_h);
    cudaGetSymbolAddress((void**)&abuf, g_agg);

    // one-time infra (streams/events are not device memory; work per call is
    // identical and fully captured into the graph via fork-join events)
    static cudaStream_t s_side = nullptr;
    static cudaEvent_t  s_fork = nullptr, s_join = nullptr;
    if (s_side == nullptr) {
        cudaStreamCreateWithFlags(&s_side, cudaStreamNonBlocking);
        cudaEventCreateWithFlags(&s_fork, cudaEventDisableTiming);
        cudaEventCreateWithFlags(&s_join, cudaEventDisableTiming);
    }

    const int nodeBlocks = (N_NODES + 255) / 256;   // 391
    const int edgeBlocks = N_EDGES / 256;           // 12500
    const int warpBlocks = N_NODES / 8;             // 12500
    const int g1Blocks   = (N_NODES + G1_ROWS - 1) / G1_ROWS;  // 391

    // ---- CSR build prefix (degrees + dinv) ----
    zero_degi_kernel<<<nodeBlocks, 256>>>();
    degi_kernel<<<edgeBlocks, 256>>>(dst);
    scan_block_kernel<<<SCAN_NBLK, SCAN_BLK>>>();   // also computes dinv

    // ---- fork: gemm1 needs only dinv; CSR tail is independent ----
    cudaEventRecord(s_fork, 0);
    cudaStreamWaitEvent(s_side, s_fork, 0);
    gemm1_kernel<<<g1Blocks, 128, 0, s_side>>>(x0, W1, hbuf);       // hh1

    scan_tops_kernel<<<1, 256>>>();
    scan_add_kernel<<<nodeBlocks, 256>>>();
    fill_kernel<<<edgeBlocks, 256>>>(src, dst);

    // ---- join: gathers need both CSR and hh1 ----
    cudaEventRecord(s_join, s_side);
    cudaStreamWaitEvent(0, s_join, 0);

    // ---- gather1 + gemm2 fused ----
    gather_gemm_kernel<<<warpBlocks, 256>>>(hbuf, b1, W2, abuf);    // hh2

    // ---- gather2 + gemm3 fused ----
    gather_gemm_kernel<<<warpBlocks, 256>>>(abuf, b2, W3, hbuf);    // hh3

    // ---- gather3 + MLP head fused ----
    gather_mlp_kernel<<<warpBlocks, 256>>>(hbuf, b3, l1W, l1b, l2W, l2b, out);
}

// round 11
// speedup vs baseline: 1.5162x; 1.1080x over previous
#include <cuda_runtime.h>
#include <cuda_bf16.h>

#define N_NODES 100000
#define N_EDGES 3200000
#define IN_FEAT 512
#define HID 32
#define SCAN_BLK 512
#define SCAN_NBLK ((N_NODES + SCAN_BLK - 1) / SCAN_BLK)   // 196

// ---------------- device scratch (static, no allocation) ----------------
__device__ int   g_degi[N_NODES];
__device__ float g_dinv[N_NODES];
__device__ int   g_rowstart[N_NODES + 1];
__device__ int   g_cursor[N_NODES];
__device__ int   g_blocksum[SCAN_NBLK];
__device__ int   g_blockoff[SCAN_NBLK];
__device__ int   g_csrc[N_EDGES];
__device__ float g_h[(size_t)N_NODES * HID];    // ping
__device__ float g_agg[(size_t)N_NODES * HID];  // pong

// ---------------- f32x2 helpers ----------------
__device__ __forceinline__ unsigned long long fma2(unsigned long long a,
                                                   unsigned long long b,
                                                   unsigned long long c) {
    unsigned long long d;
    asm("fma.rn.f32x2 %0, %1, %2, %3;" : "=l"(d) : "l"(a), "l"(b), "l"(c));
    return d;
}
__device__ __forceinline__ void unpack2(unsigned long long v, float& lo, float& hi) {
    asm("mov.b64 {%0, %1}, %2;" : "=f"(lo), "=f"(hi) : "l"(v));
}

// ---------------- degree / CSR build ----------------
__global__ void zero_degi_kernel() {
    int i = blockIdx.x * blockDim.x + threadIdx.x;
    if (i < N_NODES) g_degi[i] = 0;
}

__global__ void degi_kernel(const int* __restrict__ dst) {
    int e = blockIdx.x * blockDim.x + threadIdx.x;
    if (e < N_EDGES) atomicAdd(&g_degi[dst[e]], 1);
}

// block-local exclusive scan of degrees; also computes dinv (fused).
__global__ void scan_block_kernel() {
    __shared__ int sh[SCAN_BLK];
    int i = blockIdx.x * SCAN_BLK + threadIdx.x;
    int v = (i < N_NODES) ? g_degi[i] : 0;
    if (i < N_NODES) g_dinv[i] = rsqrtf((float)v + 1.0f);
    sh[threadIdx.x] = v;
    __syncthreads();
    #pragma unroll
    for (int off = 1; off < SCAN_BLK; off <<= 1) {
        int t = (threadIdx.x >= off) ? sh[threadIdx.x - off] : 0;
        __syncthreads();
        sh[threadIdx.x] += t;
        __syncthreads();
    }
    if (i < N_NODES) g_rowstart[i] = sh[threadIdx.x] - v;   // exclusive, block-local
    if (threadIdx.x == SCAN_BLK - 1) g_blocksum[blockIdx.x] = sh[SCAN_BLK - 1];
}

// parallel scan of the 196 block sums (single 256-thread block).
__global__ void scan_tops_kernel() {
    __shared__ int sh[256];
    int t = threadIdx.x;
    int v = (t < SCAN_NBLK) ? g_blocksum[t] : 0;
    sh[t] = v;
    __syncthreads();
    #pragma unroll
    for (int off = 1; off < 256; off <<= 1) {
        int x = (t >= off) ? sh[t - off] : 0;
        __syncthreads();
        sh[t] += x;
        __syncthreads();
    }
    if (t < SCAN_NBLK) g_blockoff[t] = sh[t] - v;   // exclusive
    if (t == 255) g_rowstart[N_NODES] = sh[255];    // == N_EDGES
}

__global__ void scan_add_kernel() {
    int i = blockIdx.x * blockDim.x + threadIdx.x;
    if (i < N_NODES) {
        int v = g_rowstart[i] + g_blockoff[i >> 9];   // 512 = 1<<9
        g_rowstart[i] = v;
        g_cursor[i] = v;
    }
}

__global__ void fill_kernel(const int* __restrict__ src, const int* __restrict__ dst) {
    int e = blockIdx.x * blockDim.x + threadIdx.x;
    if (e < N_EDGES) {
        int d = dst[e];
        int pos = atomicAdd(&g_cursor[d], 1);
        g_csrc[pos] = src[e];
    }
}

// ---------------- GEMM1: [N,512] @ [512,32], f32x2, double-buffered --------
// 256 threads, tile = 256 rows x 32 cols, K tiled by 16, 2-stage pipeline.
// Warp w: cid=w&3 (cols cid*8..+7), pgrp=w>>2; lane owns row-pairs
// pgrp*64+lane and pgrp*64+32+lane -> acc[2][8] (32 regs).
// X in shared pre-packed as row-pair float2 -> LDS.64 conflict-free;
// W duplicated (w,w) -> lane-uniform LDS.64 broadcast (1 cyc).
// LDGs for tile t+1 issued before compute of tile t (latency hidden).
#define G1_ROWS 256
#define G1_TK 16
#define G1_NT (IN_FEAT / G1_TK)   // 32 tiles
__global__ __launch_bounds__(256, 3) void gemm1_kernel(
    const float* __restrict__ x, const float* __restrict__ W,
    float* __restrict__ hh)
{
    __shared__ float2 Xp[2][G1_TK][G1_ROWS / 2];   // 32 KB
    __shared__ float2 Ws2[2][G1_TK][HID];          // 8 KB

    int tid  = threadIdx.x;
    int w    = tid >> 5;
    int lane = tid & 31;
    int cid  = w & 3;            // col group
    int pgrp = w >> 2;           // pair group (0..1)
    int rowbase = blockIdx.x * G1_ROWS;

    // LDG staging regs
    float4 xv[2];                // 2 float4 per thread per tile (512 f4 / 256 thr)
    float  wv[2];

    // addressing for loads: flat = tid + i*256 (i=0..1) -> 0..511?? need 1024 f4
    // 256 rows x 16 k = 1024 float4 -> 4 per thread
    float4 xv4[4];

    unsigned long long acc[2][8];
    #pragma unroll
    for (int g = 0; g < 2; g++)
        #pragma unroll
        for (int c = 0; c < 8; c++) acc[g][c] = 0ull;

    // ---- helpers as lambdas (inlined) ----
    auto ldg_tile = [&](int t) {
        int k0 = t * G1_TK;
        #pragma unroll
        for (int i = 0; i < 4; i++) {
            int flat = tid + i * 256;            // 0..1023
            int r  = flat >> 2;                  // 0..255
            int c4 = flat & 3;                   // 0..3
            int gr = rowbase + r;
            if (gr >= N_NODES) gr = N_NODES - 1;
            xv4[i] = *(const float4*)(x + (size_t)gr * IN_FEAT + k0 + c4 * 4);
        }
        #pragma unroll
        for (int i = 0; i < 2; i++) {
            int idx = tid + i * 256;             // 0..511
            int kk = idx >> 5;
            int c  = idx & 31;
            wv[i] = W[(size_t)(k0 + kk) * HID + c];
        }
    };
    auto sts_tile = [&](int nb) {
        #pragma unroll
        for (int i = 0; i < 4; i++) {
            int flat = tid + i * 256;
            int r  = flat >> 2;
            int c4 = flat & 3;
            int pr = r >> 1, comp = r & 1;
            (&Xp[nb][c4 * 4 + 0][pr].x)[comp] = xv4[i].x;
            (&Xp[nb][c4 * 4 + 1][pr].x)[comp] = xv4[i].y;
            (&Xp[nb][c4 * 4 + 2][pr].x)[comp] = xv4[i].z;
            (&Xp[nb][c4 * 4 + 3][pr].x)[comp] = xv4[i].w;
        }
        #pragma unroll
        for (int i = 0; i < 2; i++) {
            int idx = tid + i * 256;
            int kk = idx >> 5;
            int c  = idx & 31;
            Ws2[nb][kk][c] = make_float2(wv[i], wv[i]);
        }
    };

    // prologue: tile 0 into buf 0
    ldg_tile(0);
    sts_tile(0);
    __syncthreads();

    for (int t = 0; t < G1_NT; t++) {
        int buf = t & 1;
        if (t + 1 < G1_NT) ldg_tile(t + 1);

        #pragma unroll
        for (int kk = 0; kk < G1_TK; kk++) {
            unsigned long long xp0 =
                *(const unsigned long long*)(&Xp[buf][kk][pgrp * 64 + lane]);
            unsigned long long xp1 =
                *(const unsigned long long*)(&Xp[buf][kk][pgrp * 64 + 32 + lane]);
            #pragma unroll
            for (int c = 0; c < 8; c++) {
                unsigned long long wp =
                    *(const unsigned long long*)(&Ws2[buf][kk][cid * 8 + c]);
                acc[0][c] = fma2(xp0, wp, acc[0][c]);
                acc[1][c] = fma2(xp1, wp, acc[1][c]);
            }
        }

        if (t + 1 < G1_NT) sts_tile((t + 1) & 1);
        __syncthreads();
    }

    // epilogue: unpack, scale by dinv[row], store
    #pragma unroll
    for (int g = 0; g < 2; g++) {
        int P  = pgrp * 64 + g * 32 + lane;
        int r0 = rowbase + 2 * P;
        int r1 = r0 + 1;
        float lo[8], hi[8];
        #pragma unroll
        for (int c = 0; c < 8; c++) unpack2(acc[g][c], lo[c], hi[c]);
        if (r0 < N_NODES) {
            float d0 = g_dinv[r0];
            float4 v0 = make_float4(lo[0]*d0, lo[1]*d0, lo[2]*d0, lo[3]*d0);
            float4 v1 = make_float4(lo[4]*d0, lo[5]*d0, lo[6]*d0, lo[7]*d0);
            *(float4*)(hh + (size_t)r0 * HID + cid * 8 + 0) = v0;
            *(float4*)(hh + (size_t)r0 * HID + cid * 8 + 4) = v1;
        }
        if (r1 < N_NODES) {
            float d1 = g_dinv[r1];
            float4 v0 = make_float4(hi[0]*d1, hi[1]*d1, hi[2]*d1, hi[3]*d1);
            float4 v1 = make_float4(hi[4]*d1, hi[5]*d1, hi[6]*d1, hi[7]*d1);
            *(float4*)(hh + (size_t)r1 * HID + cid * 8 + 0) = v0;
            *(float4*)(hh + (size_t)r1 * HID + cid * 8 + 4) = v1;
        }
    }
}

// ---------------- fused gather + next-layer GEMM ----------------
__global__ __launch_bounds__(256) void gather_gemm_kernel(
    const float* __restrict__ hh_in, const float* __restrict__ b,
    const float* __restrict__ W, float* __restrict__ hh_out)
{
    __shared__ float Ws[HID * HID];   // Ws[k*32 + col] = W[k][col]
    for (int i = threadIdx.x; i < HID * HID; i += 256) Ws[i] = W[i];
    __syncthreads();

    int node = blockIdx.x * 8 + (threadIdx.x >> 5);
    int lane = threadIdx.x & 31;
    int start = g_rowstart[node];
    int end   = g_rowstart[node + 1];

    float acc0 = 0.f, acc1 = 0.f;
    for (int base = start; base < end; base += 32) {
        int e = base + lane;
        int sidx = (e < end) ? g_csrc[e] : 0;
        int n = end - base;
        if (n >= 32) {
            #pragma unroll
            for (int j = 0; j < 32; j += 2) {
                int s0 = __shfl_sync(0xffffffffu, sidx, j);
                int s1 = __shfl_sync(0xffffffffu, sidx, j + 1);
                acc0 += hh_in[(size_t)s0 * HID + lane];
                acc1 += hh_in[(size_t)s1 * HID + lane];
            }
        } else {
            for (int j = 0; j < n; j++) {
                int s = __shfl_sync(0xffffffffu, sidx, j);
                acc0 += hh_in[(size_t)s * HID + lane];
            }
        }
    }
    float dv = g_dinv[node];
    float self = hh_in[(size_t)node * HID + lane];
    float v = fmaxf(dv * (acc0 + acc1 + self) + b[lane], 0.0f);

    float o = 0.f;
    #pragma unroll
    for (int k = 0; k < HID; k++) {
        float xv = __shfl_sync(0xffffffffu, v, k);
        o += xv * Ws[k * HID + lane];
    }
    hh_out[(size_t)node * HID + lane] = o * dv;
}

// ---------------- fused layer-3 gather + MLP head ----------------
__global__ __launch_bounds__(256) void gather_mlp_kernel(
    const float* __restrict__ hh, const float* __restrict__ b3,
    const float* __restrict__ l1W, const float* __restrict__ l1b,
    const float* __restrict__ l2W, const float* __restrict__ l2b,
    float* __restrict__ out)
{
    int node = blockIdx.x * 8 + (threadIdx.x >> 5);
    int lane = threadIdx.x & 31;
    int start = g_rowstart[node];
    int end   = g_rowstart[node + 1];

    float acc0 = 0.f, acc1 = 0.f;
    for (int base = start; base < end; base += 32) {
        int e = base + lane;
        int sidx = (e < end) ? g_csrc[e] : 0;
        int n = end - base;
        if (n >= 32) {
            #pragma unroll
            for (int j = 0; j < 32; j += 2) {
                int s0 = __shfl_sync(0xffffffffu, sidx, j);
                int s1 = __shfl_sync(0xffffffffu, sidx, j + 1);
                acc0 += hh[(size_t)s0 * HID + lane];
                acc1 += hh[(size_t)s1 * HID + lane];
            }
        } else {
            for (int j = 0; j < n; j++) {
                int s = __shfl_sync(0xffffffffu, sidx, j);
                acc0 += hh[(size_t)s * HID + lane];
            }
        }
    }
    float dv = g_dinv[node];
    float self = hh[(size_t)node * HID + lane];
    float v = fmaxf(dv * (acc0 + acc1 + self) + b3[lane], 0.0f);  // x3

    // lin1: [32] -> [16], relu
    float a1 = 0.f;
    #pragma unroll
    for (int k = 0; k < 32; k++) {
        float xv = __shfl_sync(0xffffffffu, v, k);
        if (lane < 16) a1 += xv * l1W[k * 16 + lane];
    }
    float h1 = (lane < 16) ? fmaxf(a1 + l1b[lane], 0.0f) : 0.0f;

    // lin2: [16] -> [10]
    float a2 = 0.f;
    #pragma unroll
    for (int j = 0; j < 16; j++) {
        float hv = __shfl_sync(0xffffffffu, h1, j);
        if (lane < 10) a2 += hv * l2W[j * 10 + lane];
    }
    if (lane < 10) out[(size_t)node * 10 + lane] = a2 + l2b[lane];
}

// ---------------- host ----------------
extern "C" void kernel_launch(void* const* d_in, const int* in_sizes, int n_in,
                              void* d_out, int out_size)
{
    const float* x0  = (const float*)d_in[0];
    const int*   ei  = (const int*)d_in[1];   // edge_index int32
    // d_in[2] = batch (unused)
    const float* W1  = (const float*)d_in[3];
    const float* b1  = (const float*)d_in[4];
    const float* W2  = (const float*)d_in[5];
    const float* b2  = (const float*)d_in[6];
    const float* W3  = (const float*)d_in[7];
    const float* b3  = (const float*)d_in[8];
    const float* l1W = (const float*)d_in[9];
    const float* l1b = (const float*)d_in[10];
    const float* l2W = (const float*)d_in[11];
    const float* l2b = (const float*)d_in[12];
    float* out = (float*)d_out;

    const int* src = ei;
    const int* dst = ei + N_EDGES;

    float *hbuf = nullptr, *abuf = nullptr;
    cudaGetSymbolAddress((void**)&hbuf, g_h);
    cudaGetSymbolAddress((void**)&abuf, g_agg);

    // one-time infra (streams/events are not device memory; work per call is
    // identical and fully captured into the graph via fork-join events)
    static cudaStream_t s_side = nullptr;
    static cudaEvent_t  s_fork = nullptr, s_join = nullptr;
    if (s_side == nullptr) {
        cudaStreamCreateWithFlags(&s_side, cudaStreamNonBlocking);
        cudaEventCreateWithFlags(&s_fork, cudaEventDisableTiming);
        cudaEventCreateWithFlags(&s_join, cudaEventDisableTiming);
    }

    const int nodeBlocks = (N_NODES + 255) / 256;   // 391
    const int edgeBlocks = N_EDGES / 256;           // 12500
    const int warpBlocks = N_NODES / 8;             // 12500
    const int g1Blocks   = (N_NODES + G1_ROWS - 1) / G1_ROWS;  // 391

    // ---- CSR build prefix (degrees + dinv) ----
    zero_degi_kernel<<<nodeBlocks, 256>>>();
    degi_kernel<<<edgeBlocks, 256>>>(dst);
    scan_block_kernel<<<SCAN_NBLK, SCAN_BLK>>>();   // also computes dinv

    // ---- fork: gemm1 needs only dinv; CSR tail is independent ----
    cudaEventRecord(s_fork, 0);
    cudaStreamWaitEvent(s_side, s_fork, 0);
    gemm1_kernel<<<g1Blocks, 256, 0, s_side>>>(x0, W1, hbuf);       // hh1

    scan_tops_kernel<<<1, 256>>>();
    scan_add_kernel<<<nodeBlocks, 256>>>();
    fill_kernel<<<edgeBlocks, 256>>>(src, dst);

    // ---- join: gathers need both CSR and hh1 ----
    cudaEventRecord(s_join, s_side);
    cudaStreamWaitEvent(0, s_join, 0);

    // ---- gather1 + gemm2 fused ----
    gather_gemm_kernel<<<warpBlocks, 256>>>(hbuf, b1, W2, abuf);    // hh2

    // ---- gather2 + gemm3 fused ----
    gather_gemm_kernel<<<warpBlocks, 256>>>(abuf, b2, W3, hbuf);    // hh3

    // ---- gather3 + MLP head fused ----
    gather_mlp_kernel<<<warpBlocks, 256>>>(hbuf, b3, l1W, l1b, l2W, l2b, out);
}